// round 12
// baseline (speedup 1.0000x reference)
#include <cuda_runtime.h>
#include <cuda_bf16.h>
#include <cstdint>

#define NN 12288
#define EE 393216
#define INDIM 256
#define HID 64

// ---------------- static device scratch (device-code references ONLY) ---------
__device__ int   g_deg[NN];
__device__ float g_dinv[NN];
__device__ int   g_rowptr[NN + 1];
__device__ int   g_cursor[NN];
__device__ int   g_col[EE];
__device__ float g_val[EE];
__device__ float g_c[NN];
__device__ __nv_bfloat16 g_hshi[NN * HID];
__device__ __nv_bfloat16 g_hslo[NN * HID];
__device__ float g_az[NN * 32];
__device__ float g_az2[NN * 32];
__device__ float g_azcf[NN * 32];
__device__ float g_t1[NN * 64];
__device__ float g_t2[NN * 64];
__device__ float g_t3[NN * 64];
__device__ float g_at1[NN * 64];
__device__ float g_at2[NN * 64];
__device__ float g_at3[NN * 64];

// ---------------- CSR build ---------------------------------------------------
// zero degrees + cvec fused (both independent first-wave work)
__global__ void k_init0(const float* __restrict__ x) {
    int i = blockIdx.x * blockDim.x + threadIdx.x;
    if (i < NN) {
        g_deg[i] = 0;
        g_c[i] = 1.0f - 2.0f * x[i * INDIM];
    }
}
__global__ void k_count(const int* __restrict__ ei) {
    int e2 = (blockIdx.x * blockDim.x + threadIdx.x) * 2;
    if (e2 >= EE) return;
    int2 d = *reinterpret_cast<const int2*>(&ei[EE + e2]);
    atomicAdd(&g_deg[d.x], 1);
    atomicAdd(&g_deg[d.y], 1);
}
// scan + dinv fused; vectorized degree loads
__global__ void k_scan() {
    __shared__ int wsum[32];
    int t = threadIdx.x;
    int base = t * 12;
    int4 d0 = *reinterpret_cast<int4*>(&g_deg[base]);
    int4 d1 = *reinterpret_cast<int4*>(&g_deg[base + 4]);
    int4 d2 = *reinterpret_cast<int4*>(&g_deg[base + 8]);
    int dv[12] = {d0.x, d0.y, d0.z, d0.w, d1.x, d1.y, d1.z, d1.w,
                  d2.x, d2.y, d2.z, d2.w};
    int loc[12];
    int s = 0;
#pragma unroll
    for (int i = 0; i < 12; i++) { loc[i] = s; s += dv[i]; }
    int lane = t & 31, wid = t >> 5;
    int v = s;
#pragma unroll
    for (int o = 1; o < 32; o <<= 1) {
        int u = __shfl_up_sync(0xffffffffu, v, o);
        if (lane >= o) v += u;
    }
    if (lane == 31) wsum[wid] = v;
    __syncthreads();
    if (wid == 0) {
        int w = wsum[lane];
#pragma unroll
        for (int o = 1; o < 32; o <<= 1) {
            int u = __shfl_up_sync(0xffffffffu, w, o);
            if (lane >= o) w += u;
        }
        wsum[lane] = w;
    }
    __syncthreads();
    int excl = v - s + (wid > 0 ? wsum[wid - 1] : 0);
#pragma unroll
    for (int i = 0; i < 12; i++) {
        g_rowptr[base + i] = excl + loc[i];
        g_cursor[base + i] = excl + loc[i];
        g_dinv[base + i] = rsqrtf((float)dv[i] + 1.0f);
    }
    if (t == 1023) g_rowptr[NN] = excl + s;
}
__global__ void k_scatter(const int* __restrict__ ei) {
    int e2 = (blockIdx.x * blockDim.x + threadIdx.x) * 2;
    if (e2 >= EE) return;
    int2 s = *reinterpret_cast<const int2*>(&ei[e2]);
    int2 d = *reinterpret_cast<const int2*>(&ei[EE + e2]);
    int p0 = atomicAdd(&g_cursor[d.x], 1);
    g_col[p0] = s.x;
    g_val[p0] = g_dinv[s.x] * g_dinv[d.x];
    int p1 = atomicAdd(&g_cursor[d.y], 1);
    g_col[p1] = s.y;
    g_val[p1] = g_dinv[s.y] * g_dinv[d.y];
}

// ---------------- CSR gather aggregations (pipelined 4x edge loops) -----------
// y1 aggregation + scalar c aggregation + FUSED h1/h1cf epilogue
__global__ void k_agg64c(const float* __restrict__ in, const float* __restrict__ W1,
                         const float* __restrict__ b1, float* __restrict__ h1,
                         float* __restrict__ h1cf) {
    int w = (blockIdx.x * 256 + threadIdx.x) >> 5;
    int lane = threadIdx.x & 31;
    if (w >= NN) return;
    int s0 = g_rowptr[w], s1 = g_rowptr[w + 1];
    float2 a = make_float2(0.f, 0.f);
    float cacc = 0.f;
    int j = s0;
    for (; j + 4 <= s1; j += 4) {
        int sA = g_col[j], sB = g_col[j + 1], sC = g_col[j + 2], sD = g_col[j + 3];
        float wA = g_val[j], wB = g_val[j + 1], wC = g_val[j + 2], wD = g_val[j + 3];
        float2 vA = reinterpret_cast<const float2*>(in + sA * 64)[lane];
        float2 vB = reinterpret_cast<const float2*>(in + sB * 64)[lane];
        float2 vC = reinterpret_cast<const float2*>(in + sC * 64)[lane];
        float2 vD = reinterpret_cast<const float2*>(in + sD * 64)[lane];
        float cA = g_c[sA], cB = g_c[sB], cC = g_c[sC], cD = g_c[sD];
        a.x += wA * vA.x;  a.y += wA * vA.y;  cacc += wA * cA;
        a.x += wB * vB.x;  a.y += wB * vB.y;  cacc += wB * cB;
        a.x += wC * vC.x;  a.y += wC * vC.y;  cacc += wC * cC;
        a.x += wD * vD.x;  a.y += wD * vD.y;  cacc += wD * cD;
    }
    for (; j < s1; j++) {
        int s = g_col[j];
        float wt = g_val[j];
        float2 v = reinterpret_cast<const float2*>(in + s * 64)[lane];
        a.x += wt * v.x;  a.y += wt * v.y;
        cacc += wt * g_c[s];
    }
    float ws = g_dinv[w] * g_dinv[w];
    float2 v = reinterpret_cast<const float2*>(in + w * 64)[lane];
    a.x += ws * v.x;  a.y += ws * v.y;
    float aggc = cacc + ws * g_c[w];
    float2 bb = reinterpret_cast<const float2*>(b1)[lane];
    float2 w0 = reinterpret_cast<const float2*>(W1)[lane];  // enc_W1 row 0
    float2 h, hcf;
    h.x   = fmaxf(a.x + bb.x, 0.f);
    h.y   = fmaxf(a.y + bb.y, 0.f);
    hcf.x = fmaxf(a.x + aggc * w0.x + bb.x, 0.f);
    hcf.y = fmaxf(a.y + aggc * w0.y + bb.y, 0.f);
    reinterpret_cast<float2*>(h1 + w * 64)[lane] = h;
    reinterpret_cast<float2*>(h1cf + w * 64)[lane] = hcf;
}
__global__ void k_agg64x2(const float* __restrict__ in1, const float* __restrict__ in2,
                          float* __restrict__ out1, float* __restrict__ out2) {
    int w = (blockIdx.x * 256 + threadIdx.x) >> 5;
    int lane = threadIdx.x & 31;
    if (w >= NN) return;
    int s0 = g_rowptr[w], s1 = g_rowptr[w + 1];
    float2 a = make_float2(0.f, 0.f), b = make_float2(0.f, 0.f);
    int j = s0;
    for (; j + 4 <= s1; j += 4) {
        int sA = g_col[j], sB = g_col[j + 1], sC = g_col[j + 2], sD = g_col[j + 3];
        float wA = g_val[j], wB = g_val[j + 1], wC = g_val[j + 2], wD = g_val[j + 3];
        float2 p1A = reinterpret_cast<const float2*>(in1 + sA * 64)[lane];
        float2 p2A = reinterpret_cast<const float2*>(in2 + sA * 64)[lane];
        float2 p1B = reinterpret_cast<const float2*>(in1 + sB * 64)[lane];
        float2 p2B = reinterpret_cast<const float2*>(in2 + sB * 64)[lane];
        float2 p1C = reinterpret_cast<const float2*>(in1 + sC * 64)[lane];
        float2 p2C = reinterpret_cast<const float2*>(in2 + sC * 64)[lane];
        float2 p1D = reinterpret_cast<const float2*>(in1 + sD * 64)[lane];
        float2 p2D = reinterpret_cast<const float2*>(in2 + sD * 64)[lane];
        a.x += wA * p1A.x;  a.y += wA * p1A.y;  b.x += wA * p2A.x;  b.y += wA * p2A.y;
        a.x += wB * p1B.x;  a.y += wB * p1B.y;  b.x += wB * p2B.x;  b.y += wB * p2B.y;
        a.x += wC * p1C.x;  a.y += wC * p1C.y;  b.x += wC * p2C.x;  b.y += wC * p2C.y;
        a.x += wD * p1D.x;  a.y += wD * p1D.y;  b.x += wD * p2D.x;  b.y += wD * p2D.y;
    }
    for (; j < s1; j++) {
        int s = g_col[j];
        float wt = g_val[j];
        float2 v1 = reinterpret_cast<const float2*>(in1 + s * 64)[lane];
        float2 v2 = reinterpret_cast<const float2*>(in2 + s * 64)[lane];
        a.x += wt * v1.x;  a.y += wt * v1.y;
        b.x += wt * v2.x;  b.y += wt * v2.y;
    }
    float ws = g_dinv[w] * g_dinv[w];
    float2 v1 = reinterpret_cast<const float2*>(in1 + w * 64)[lane];
    float2 v2 = reinterpret_cast<const float2*>(in2 + w * 64)[lane];
    a.x += ws * v1.x;  a.y += ws * v1.y;
    b.x += ws * v2.x;  b.y += ws * v2.y;
    reinterpret_cast<float2*>(out1 + w * 64)[lane] = a;
    reinterpret_cast<float2*>(out2 + w * 64)[lane] = b;
}
__global__ void k_agg64x3() {
    int w = (blockIdx.x * 256 + threadIdx.x) >> 5;
    int lane = threadIdx.x & 31;
    if (w >= NN) return;
    int s0 = g_rowptr[w], s1 = g_rowptr[w + 1];
    float2 a = make_float2(0.f, 0.f), b = make_float2(0.f, 0.f), c = make_float2(0.f, 0.f);
    int j = s0;
    for (; j + 2 <= s1; j += 2) {
        int sA = g_col[j], sB = g_col[j + 1];
        float wA = g_val[j], wB = g_val[j + 1];
        float2 v1A = reinterpret_cast<const float2*>(g_t1 + sA * 64)[lane];
        float2 v2A = reinterpret_cast<const float2*>(g_t2 + sA * 64)[lane];
        float2 v3A = reinterpret_cast<const float2*>(g_t3 + sA * 64)[lane];
        float2 v1B = reinterpret_cast<const float2*>(g_t1 + sB * 64)[lane];
        float2 v2B = reinterpret_cast<const float2*>(g_t2 + sB * 64)[lane];
        float2 v3B = reinterpret_cast<const float2*>(g_t3 + sB * 64)[lane];
        a.x += wA * v1A.x;  a.y += wA * v1A.y;
        b.x += wA * v2A.x;  b.y += wA * v2A.y;
        c.x += wA * v3A.x;  c.y += wA * v3A.y;
        a.x += wB * v1B.x;  a.y += wB * v1B.y;
        b.x += wB * v2B.x;  b.y += wB * v2B.y;
        c.x += wB * v3B.x;  c.y += wB * v3B.y;
    }
    for (; j < s1; j++) {
        int s = g_col[j];
        float wt = g_val[j];
        float2 v1 = reinterpret_cast<const float2*>(g_t1 + s * 64)[lane];
        float2 v2 = reinterpret_cast<const float2*>(g_t2 + s * 64)[lane];
        float2 v3 = reinterpret_cast<const float2*>(g_t3 + s * 64)[lane];
        a.x += wt * v1.x;  a.y += wt * v1.y;
        b.x += wt * v2.x;  b.y += wt * v2.y;
        c.x += wt * v3.x;  c.y += wt * v3.y;
    }
    float ws = g_dinv[w] * g_dinv[w];
    float2 v1 = reinterpret_cast<const float2*>(g_t1 + w * 64)[lane];
    float2 v2 = reinterpret_cast<const float2*>(g_t2 + w * 64)[lane];
    float2 v3 = reinterpret_cast<const float2*>(g_t3 + w * 64)[lane];
    a.x += ws * v1.x;  a.y += ws * v1.y;
    b.x += ws * v2.x;  b.y += ws * v2.y;
    c.x += ws * v3.x;  c.y += ws * v3.y;
    reinterpret_cast<float2*>(g_at1 + w * 64)[lane] = a;
    reinterpret_cast<float2*>(g_at2 + w * 64)[lane] = b;
    reinterpret_cast<float2*>(g_at3 + w * 64)[lane] = c;
}
__global__ void k_agg96(const float* __restrict__ z, const float* __restrict__ zcf) {
    int w = (blockIdx.x * 256 + threadIdx.x) >> 5;
    int lane = threadIdx.x & 31;
    if (w >= NN) return;
    int s0 = g_rowptr[w], s1 = g_rowptr[w + 1];
    float2 a = make_float2(0.f, 0.f);
    float c0 = 0.f;
    int j = s0;
    for (; j + 4 <= s1; j += 4) {
        int sA = g_col[j], sB = g_col[j + 1], sC = g_col[j + 2], sD = g_col[j + 3];
        float wA = g_val[j], wB = g_val[j + 1], wC = g_val[j + 2], wD = g_val[j + 3];
        float2 vA = reinterpret_cast<const float2*>(z + sA * 64)[lane];
        float2 vB = reinterpret_cast<const float2*>(z + sB * 64)[lane];
        float2 vC = reinterpret_cast<const float2*>(z + sC * 64)[lane];
        float2 vD = reinterpret_cast<const float2*>(z + sD * 64)[lane];
        float cA = zcf[sA * 64 + lane], cB = zcf[sB * 64 + lane];
        float cC = zcf[sC * 64 + lane], cD = zcf[sD * 64 + lane];
        a.x += wA * vA.x;  a.y += wA * vA.y;  c0 += wA * cA;
        a.x += wB * vB.x;  a.y += wB * vB.y;  c0 += wB * cB;
        a.x += wC * vC.x;  a.y += wC * vC.y;  c0 += wC * cC;
        a.x += wD * vD.x;  a.y += wD * vD.y;  c0 += wD * cD;
    }
    for (; j < s1; j++) {
        int s = g_col[j];
        float wt = g_val[j];
        float2 v = reinterpret_cast<const float2*>(z + s * 64)[lane];
        a.x += wt * v.x;  a.y += wt * v.y;
        c0 += wt * zcf[s * 64 + lane];
    }
    float ws = g_dinv[w] * g_dinv[w];
    float2 v = reinterpret_cast<const float2*>(z + w * 64)[lane];
    a.x += ws * v.x;  a.y += ws * v.y;
    c0 += ws * zcf[w * 64 + lane];
    if (lane < 16) reinterpret_cast<float2*>(g_az + w * 32)[lane] = a;
    else           reinterpret_cast<float2*>(g_az2 + w * 32)[lane - 16] = a;
    g_azcf[w * 32 + lane] = c0;
}

// ---------------- GEMM bodies -------------------------------------------------
template <int KIN, int KOUT>
__device__ __forceinline__ float4 gemm4_compute(const float* __restrict__ A,
                                                const float* __restrict__ W,
                                                const float* __restrict__ b,
                                                int row, int c4) {
    float4 acc;
    if (b) { acc.x = b[c4]; acc.y = b[c4 + 1]; acc.z = b[c4 + 2]; acc.w = b[c4 + 3]; }
    else   { acc.x = acc.y = acc.z = acc.w = 0.f; }
    const float4* a4 = reinterpret_cast<const float4*>(A + row * KIN);
#pragma unroll 4
    for (int k4 = 0; k4 < KIN / 4; k4++) {
        float4 av = a4[k4];
        float4 w0 = *reinterpret_cast<const float4*>(&W[(k4 * 4 + 0) * KOUT + c4]);
        float4 w1 = *reinterpret_cast<const float4*>(&W[(k4 * 4 + 1) * KOUT + c4]);
        float4 w2 = *reinterpret_cast<const float4*>(&W[(k4 * 4 + 2) * KOUT + c4]);
        float4 w3 = *reinterpret_cast<const float4*>(&W[(k4 * 4 + 3) * KOUT + c4]);
        acc.x += av.x * w0.x + av.y * w1.x + av.z * w2.x + av.w * w3.x;
        acc.y += av.x * w0.y + av.y * w1.y + av.z * w2.y + av.w * w3.y;
        acc.z += av.x * w0.z + av.y * w1.z + av.z * w2.z + av.w * w3.z;
        acc.w += av.x * w0.w + av.y * w1.w + av.z * w2.w + av.w * w3.w;
    }
    return acc;
}
template <int KIN, int KOUT, bool RELU>
__global__ void k_gemm4(const float* __restrict__ A, const float* __restrict__ W,
                        const float* __restrict__ b, float* __restrict__ out) {
    constexpr int C4 = KOUT / 4;
    int idx = blockIdx.x * 256 + threadIdx.x;
    if (idx >= NN * C4) return;
    int row = idx / C4, c4 = (idx % C4) * 4;
    float4 acc = gemm4_compute<KIN, KOUT>(A, W, b, row, c4);
    if (RELU) {
        acc.x = fmaxf(acc.x, 0.f); acc.y = fmaxf(acc.y, 0.f);
        acc.z = fmaxf(acc.z, 0.f); acc.w = fmaxf(acc.w, 0.f);
    }
    *reinterpret_cast<float4*>(&out[row * KOUT + c4]) = acc;
}
// z GEMM with fused z_s / z_ns split outputs
__global__ void k_gemmz(const float* __restrict__ A, const float* __restrict__ W,
                        const float* __restrict__ b, float* __restrict__ z,
                        float* __restrict__ ozs, float* __restrict__ ozns) {
    int idx = blockIdx.x * 256 + threadIdx.x;
    if (idx >= NN * 16) return;
    int row = idx / 16, c4 = (idx % 16) * 4;
    float4 acc = gemm4_compute<64, 64>(A, W, b, row, c4);
    *reinterpret_cast<float4*>(&z[row * 64 + c4]) = acc;
    if (c4 < 32) *reinterpret_cast<float4*>(&ozs[row * 32 + c4]) = acc;
    else         *reinterpret_cast<float4*>(&ozns[row * 32 + c4 - 32]) = acc;
}
// four 32->64 GEMMs; v==3 (hs) emits bf16 hi/lo
__global__ void k_dec1(const float* __restrict__ d1W1, const float* __restrict__ d1b1,
                       const float* __restrict__ d2W1, const float* __restrict__ d2b1,
                       const float* __restrict__ sW, const float* __restrict__ sb) {
    int v = blockIdx.y;
    int idx = blockIdx.x * 256 + threadIdx.x;
    if (idx >= NN * 16) return;
    int row = idx / 16, c4 = (idx % 16) * 4;
    const float* A = (v == 0) ? g_az : (v == 2) ? g_azcf : g_az2;
    const float* W = (v == 1) ? d2W1 : (v == 3) ? sW : d1W1;
    const float* b = (v == 1) ? d2b1 : (v == 3) ? sb : d1b1;
    float4 acc = gemm4_compute<32, 64>(A, W, b, row, c4);
    if (v == 3) {
        float vals[4] = {acc.x, acc.y, acc.z, acc.w};
#pragma unroll
        for (int q = 0; q < 4; q++) {
            __nv_bfloat16 hi = __float2bfloat16(vals[q]);
            g_hshi[row * 64 + c4 + q] = hi;
            g_hslo[row * 64 + c4 + q] = __float2bfloat16(vals[q] - __bfloat162float(hi));
        }
    } else {
        acc.x = fmaxf(acc.x, 0.f); acc.y = fmaxf(acc.y, 0.f);
        acc.z = fmaxf(acc.z, 0.f); acc.w = fmaxf(acc.w, 0.f);
        float* out = (v == 0) ? g_t1 : (v == 1) ? g_t2 : g_t3;
        *reinterpret_cast<float4*>(&out[row * 64 + c4]) = acc;
    }
}
// three 64->256 GEMMs in one launch
__global__ void k_decout(const float* __restrict__ W1, const float* __restrict__ W2,
                         const float* __restrict__ b1, const float* __restrict__ b2,
                         float* __restrict__ o1, float* __restrict__ o2,
                         float* __restrict__ o3) {
    int v = blockIdx.y;
    int idx = blockIdx.x * 256 + threadIdx.x;
    if (idx >= NN * 64) return;
    int row = idx / 64, c4 = (idx % 64) * 4;
    const float* A = (v == 0) ? g_at1 : (v == 1) ? g_at2 : g_at3;
    const float* W = (v == 1) ? W2 : W1;
    const float* b = (v == 1) ? b2 : b1;
    float* out = (v == 0) ? o1 : (v == 1) ? o2 : o3;
    float4 acc = gemm4_compute<64, 256>(A, W, b, row, c4);
    *reinterpret_cast<float4*>(&out[row * 256 + c4]) = acc;
}

// ---------------- SYRK via mma.sync bf16 (hi/lo 3-product compensation) -------
#define SPITCH 72
#define TBYTES (128 * SPITCH * 2)   // 18432
#define OPITCH 133
#define NT 96                        // tile rows (NN/128)
#define NTRI (NT * (NT + 1) / 2)     // 4656 upper-triangular tiles

static __device__ __forceinline__ void mma_bf16(float* d, const uint32_t* a,
                                                uint32_t b0, uint32_t b1) {
    asm volatile(
        "mma.sync.aligned.m16n8k16.row.col.f32.bf16.bf16.f32 "
        "{%0,%1,%2,%3}, {%4,%5,%6,%7}, {%8,%9}, {%0,%1,%2,%3};"
        : "+f"(d[0]), "+f"(d[1]), "+f"(d[2]), "+f"(d[3])
        : "r"(a[0]), "r"(a[1]), "r"(a[2]), "r"(a[3]), "r"(b0), "r"(b1));
}

__global__ void __launch_bounds__(256) k_syrk_mma(float* __restrict__ C) {
    // triangular decode: block t -> (bi, bj), bj >= bi
    int t = blockIdx.x;
    int bi = (int)((2.0 * NT + 1.0 - sqrt((2.0 * NT + 1.0) * (2.0 * NT + 1.0) - 8.0 * t)) * 0.5);
    while (NT * bi - bi * (bi - 1) / 2 > t) bi--;
    while (NT * (bi + 1) - (bi + 1) * bi / 2 <= t) bi++;
    int bj = bi + (t - (NT * bi - bi * (bi - 1) / 2));

    extern __shared__ char smem[];
    __nv_bfloat16* sAhi = reinterpret_cast<__nv_bfloat16*>(smem);
    __nv_bfloat16* sAlo = reinterpret_cast<__nv_bfloat16*>(smem + TBYTES);
    __nv_bfloat16* sBhi = reinterpret_cast<__nv_bfloat16*>(smem + 2 * TBYTES);
    __nv_bfloat16* sBlo = reinterpret_cast<__nv_bfloat16*>(smem + 3 * TBYTES);
    int tid = threadIdx.x;

    {
        const uint4* ga_hi = reinterpret_cast<const uint4*>(g_hshi + (size_t)bi * 128 * 64);
        const uint4* ga_lo = reinterpret_cast<const uint4*>(g_hslo + (size_t)bi * 128 * 64);
        const uint4* gb_hi = reinterpret_cast<const uint4*>(g_hshi + (size_t)bj * 128 * 64);
        const uint4* gb_lo = reinterpret_cast<const uint4*>(g_hslo + (size_t)bj * 128 * 64);
        for (int idx = tid; idx < 1024; idx += 256) {
            int row = idx >> 3, ch = idx & 7;
            int so = row * SPITCH + ch * 8;
            *reinterpret_cast<uint4*>(sAhi + so) = ga_hi[idx];
            *reinterpret_cast<uint4*>(sAlo + so) = ga_lo[idx];
            *reinterpret_cast<uint4*>(sBhi + so) = gb_hi[idx];
            *reinterpret_cast<uint4*>(sBlo + so) = gb_lo[idx];
        }
    }
    __syncthreads();

    int wid = tid >> 5, lane = tid & 31;
    int wr = wid >> 1, wc = wid & 1;
    int g = lane >> 2, tg = lane & 3;

    float acc[2][8][4];
#pragma unroll
    for (int mt = 0; mt < 2; mt++)
#pragma unroll
        for (int nt = 0; nt < 8; nt++)
#pragma unroll
            for (int q = 0; q < 4; q++) acc[mt][nt][q] = 0.f;

#pragma unroll
    for (int ks = 0; ks < 4; ks++) {
        int k0 = ks * 16;
        uint32_t aHi[2][4], aLo[2][4];
#pragma unroll
        for (int mt = 0; mt < 2; mt++) {
            int r = wr * 32 + mt * 16;
            aHi[mt][0] = *reinterpret_cast<const uint32_t*>(&sAhi[(r + g) * SPITCH + k0 + tg * 2]);
            aHi[mt][1] = *reinterpret_cast<const uint32_t*>(&sAhi[(r + g + 8) * SPITCH + k0 + tg * 2]);
            aHi[mt][2] = *reinterpret_cast<const uint32_t*>(&sAhi[(r + g) * SPITCH + k0 + tg * 2 + 8]);
            aHi[mt][3] = *reinterpret_cast<const uint32_t*>(&sAhi[(r + g + 8) * SPITCH + k0 + tg * 2 + 8]);
            aLo[mt][0] = *reinterpret_cast<const uint32_t*>(&sAlo[(r + g) * SPITCH + k0 + tg * 2]);
            aLo[mt][1] = *reinterpret_cast<const uint32_t*>(&sAlo[(r + g + 8) * SPITCH + k0 + tg * 2]);
            aLo[mt][2] = *reinterpret_cast<const uint32_t*>(&sAlo[(r + g) * SPITCH + k0 + tg * 2 + 8]);
            aLo[mt][3] = *reinterpret_cast<const uint32_t*>(&sAlo[(r + g + 8) * SPITCH + k0 + tg * 2 + 8]);
        }
#pragma unroll
        for (int nt = 0; nt < 8; nt++) {
            int n = wc * 64 + nt * 8 + g;
            uint32_t bh0 = *reinterpret_cast<const uint32_t*>(&sBhi[n * SPITCH + k0 + tg * 2]);
            uint32_t bh1 = *reinterpret_cast<const uint32_t*>(&sBhi[n * SPITCH + k0 + tg * 2 + 8]);
            uint32_t bl0 = *reinterpret_cast<const uint32_t*>(&sBlo[n * SPITCH + k0 + tg * 2]);
            uint32_t bl1 = *reinterpret_cast<const uint32_t*>(&sBlo[n * SPITCH + k0 + tg * 2 + 8]);
#pragma unroll
            for (int mt = 0; mt < 2; mt++) {
                mma_bf16(acc[mt][nt], aHi[mt], bh0, bh1);
                mma_bf16(acc[mt][nt], aHi[mt], bl0, bl1);
                mma_bf16(acc[mt][nt], aLo[mt], bh0, bh1);
            }
        }
    }
    __syncthreads();

    float* stage = reinterpret_cast<float*>(smem);   // [128][OPITCH]
#pragma unroll
    for (int mt = 0; mt < 2; mt++) {
        int r = wr * 32 + mt * 16 + g;
#pragma unroll
        for (int nt = 0; nt < 8; nt++) {
            int cc = wc * 64 + nt * 8 + tg * 2;
            stage[r * OPITCH + cc]           = acc[mt][nt][0];
            stage[r * OPITCH + cc + 1]       = acc[mt][nt][1];
            stage[(r + 8) * OPITCH + cc]     = acc[mt][nt][2];
            stage[(r + 8) * OPITCH + cc + 1] = acc[mt][nt][3];
        }
    }
    __syncthreads();

    for (int idx = tid; idx < 128 * 128; idx += 256) {
        int r2 = idx >> 7, c2 = idx & 127;
        C[(size_t)(bi * 128 + r2) * NN + bj * 128 + c2] = stage[r2 * OPITCH + c2];
    }
    if (bi != bj) {
        for (int idx = tid; idx < 128 * 128; idx += 256) {
            int r2 = idx >> 7, c2 = idx & 127;
            C[(size_t)(bj * 128 + r2) * NN + bi * 128 + c2] = stage[c2 * OPITCH + r2];
        }
    }
}

// ---------------- input-order hypotheses (round-3 validated) ------------------
static const int SIGS[6][16] = {
  {3145728,786432,16384,64,4096,64,2048,64,16384,256,2048,64,16384,256,2048,64},
  {2048,16384,64,256,2048,16384,64,256,786432,16384,4096,64,64,2048,64,3145728},
  {64,256,2048,16384,64,256,2048,16384,786432,64,64,16384,4096,64,2048,3145728},
  {64,2048,256,16384,64,2048,256,16384,64,2048,64,4096,64,16384,786432,3145728},
  {3145728,786432,16384,16384,16384,4096,2048,2048,2048,256,256,64,64,64,64,64},
  {64,64,64,64,64,256,256,2048,2048,2048,4096,16384,16384,16384,786432,3145728},
};
static const int MAPS[6][16] = {
  {0,1,2,3,4,5,6,7,8,9,10,11,12,13,14,15},
  {15,8,9,11,10,12,0,2,1,3,4,6,5,7,13,14},
  {15,8,11,9,12,10,2,0,3,1,6,4,7,5,14,13},
  {15,14,13,12,11,10,9,8,7,6,5,4,3,2,1,0},
  {0,1,2,11,5,12,6,13,3,9,7,14,4,10,8,15},
  {15,14,11,0,10,1,7,2,12,5,8,3,13,6,9,4},
};

// ---------------- launch ------------------------------------------------------
extern "C" void kernel_launch(void* const* d_in, const int* in_sizes, int n_in,
                              void* d_out, int out_size) {
    static bool init_done = false;
    if (!init_done) {
        cudaFuncSetAttribute(k_syrk_mma, cudaFuncAttributeMaxDynamicSharedMemorySize,
                             4 * TBYTES);
        init_done = true;
    }

    const int* map = MAPS[0];
    for (int h = 0; h < 6; h++) {
        bool ok = (n_in >= 16);
        for (int i = 0; ok && i < 16; i++) ok = (in_sizes[i] == SIGS[h][i]);
        if (ok) { map = MAPS[h]; break; }
    }
    const float* x      = (const float*)d_in[map[0]];
    const int*   ei     = (const int*)  d_in[map[1]];
    const float* enc_W1 = (const float*)d_in[map[2]];
    const float* enc_b1 = (const float*)d_in[map[3]];
    const float* enc_W2 = (const float*)d_in[map[4]];
    const float* enc_b2 = (const float*)d_in[map[5]];
    const float* d1_W1  = (const float*)d_in[map[6]];
    const float* d1_b1  = (const float*)d_in[map[7]];
    const float* d1_W2  = (const float*)d_in[map[8]];
    const float* d1_b2  = (const float*)d_in[map[9]];
    const float* d2_W1  = (const float*)d_in[map[10]];
    const float* d2_b1  = (const float*)d_in[map[11]];
    const float* d2_W2  = (const float*)d_in[map[12]];
    const float* d2_b2  = (const float*)d_in[map[13]];
    const float* s_W    = (const float*)d_in[map[14]];
    const float* s_b    = (const float*)d_in[map[15]];
    float* out = (float*)d_out;

    float* o_zs   = out;
    float* o_zns  = out + (size_t)NN * 32;
    float* o_xs   = out + (size_t)NN * 64;
    float* o_xns  = o_xs + (size_t)NN * 256;
    float* o_xscf = o_xns + (size_t)NN * 256;
    float* o_s    = o_xscf + (size_t)NN * 256;   // [N,N] written LAST

    // encoder scratch in o_s (all consumed before SYRK)
    const size_t CH = (size_t)NN * 64;
    float* sc_y1   = o_s + 0 * CH;
    float* sc_h1   = o_s + 1 * CH;
    float* sc_h1cf = o_s + 2 * CH;
    float* sc_B    = o_s + 3 * CH;
    float* sc_Bcf  = o_s + 4 * CH;
    float* sc_z    = o_s + 5 * CH;
    float* sc_zcf  = o_s + 6 * CH;

    const int TB = 256;
    const int gN   = (NN + TB - 1) / TB;
    const int gE2  = (EE / 2 + TB - 1) / TB;
    const int gN32 = (NN * 32 + TB - 1) / TB;
    const int gN64 = (NN * 64 + TB - 1) / TB;
    const int gN16 = (NN * 16 + TB - 1) / TB;

    // CSR build (+ fused cvec)
    k_init0<<<gN, TB>>>(x);
    k_count<<<gE2, TB>>>(ei);
    k_scan<<<1, 1024>>>();
    k_scatter<<<gE2, TB>>>(ei);

    // encoder conv1 (GEMM + fused agg/h1)
    k_gemm4<INDIM, 64, false><<<gN16, TB>>>(x, enc_W1, nullptr, sc_y1);
    k_agg64c<<<gN32, TB>>>(sc_y1, enc_W1, enc_b1, sc_h1, sc_h1cf);

    // encoder conv2 (fused split in gemmz)
    k_agg64x2<<<gN32, TB>>>(sc_h1, sc_h1cf, sc_B, sc_Bcf);
    k_gemmz<<<gN16, TB>>>(sc_B, enc_W2, enc_b2, sc_z, o_zs, o_zns);
    k_gemm4<64, 64, false><<<gN16, TB>>>(sc_Bcf, enc_W2, enc_b2, sc_zcf);

    // fused aggregation of z_s / z_ns / z_s_cf
    k_agg96<<<gN32, TB>>>(sc_z, sc_zcf);

    // decoder first layers + hs (v==3 writes bf16 hi/lo)
    dim3 dg1(gN16, 4);
    k_dec1<<<dg1, TB>>>(d1_W1, d1_b1, d2_W1, d2_b1, s_W, s_b);

    // decoder tail
    k_agg64x3<<<gN32, TB>>>();
    dim3 dog(gN64, 3);
    k_decout<<<dog, TB>>>(d1_W2, d2_W2, d1_b2, d2_b2, o_xs, o_xns, o_xscf);

    // tensor-core SYRK last (triangular grid)
    k_syrk_mma<<<NTRI, 256, 4 * TBYTES>>>(o_s);
}

// round 13
// speedup vs baseline: 1.0938x; 1.0938x over previous
#include <cuda_runtime.h>
#include <cuda_bf16.h>
#include <cstdint>

#define NN 12288
#define EE 393216
#define INDIM 256
#define HID 64

// ---------------- static device scratch (device-code references ONLY) ---------
__device__ int   g_deg[NN];
__device__ float g_dinv[NN];
__device__ int   g_rowptr[NN + 1];
__device__ int   g_cursor[NN];
__device__ int   g_col[EE];
__device__ float g_val[EE];
__device__ float g_c[NN];
__device__ __nv_bfloat16 g_hshi[NN * HID];
__device__ __nv_bfloat16 g_hslo[NN * HID];
__device__ float g_az[NN * 32];
__device__ float g_az2[NN * 32];
__device__ float g_azcf[NN * 32];
__device__ float g_t1[NN * 64];
__device__ float g_t2[NN * 64];
__device__ float g_t3[NN * 64];
__device__ float g_at1[NN * 64];
__device__ float g_at2[NN * 64];
__device__ float g_at3[NN * 64];

// ---------------- CSR build ---------------------------------------------------
// zero degrees + cvec fused
__global__ void k_init0(const float* __restrict__ x) {
    int i = blockIdx.x * blockDim.x + threadIdx.x;
    if (i < NN) {
        g_deg[i] = 0;
        g_c[i] = 1.0f - 2.0f * x[i * INDIM];
    }
}
__global__ void k_count(const int* __restrict__ ei) {
    int e = blockIdx.x * blockDim.x + threadIdx.x;
    if (e < EE) atomicAdd(&g_deg[ei[EE + e]], 1);
}
// scan + dinv fused; vectorized degree loads
__global__ void k_scan() {
    __shared__ int wsum[32];
    int t = threadIdx.x;
    int base = t * 12;
    int4 d0 = *reinterpret_cast<int4*>(&g_deg[base]);
    int4 d1 = *reinterpret_cast<int4*>(&g_deg[base + 4]);
    int4 d2 = *reinterpret_cast<int4*>(&g_deg[base + 8]);
    int dv[12] = {d0.x, d0.y, d0.z, d0.w, d1.x, d1.y, d1.z, d1.w,
                  d2.x, d2.y, d2.z, d2.w};
    int loc[12];
    int s = 0;
#pragma unroll
    for (int i = 0; i < 12; i++) { loc[i] = s; s += dv[i]; }
    int lane = t & 31, wid = t >> 5;
    int v = s;
#pragma unroll
    for (int o = 1; o < 32; o <<= 1) {
        int u = __shfl_up_sync(0xffffffffu, v, o);
        if (lane >= o) v += u;
    }
    if (lane == 31) wsum[wid] = v;
    __syncthreads();
    if (wid == 0) {
        int w = wsum[lane];
#pragma unroll
        for (int o = 1; o < 32; o <<= 1) {
            int u = __shfl_up_sync(0xffffffffu, w, o);
            if (lane >= o) w += u;
        }
        wsum[lane] = w;
    }
    __syncthreads();
    int excl = v - s + (wid > 0 ? wsum[wid - 1] : 0);
#pragma unroll
    for (int i = 0; i < 12; i++) {
        g_rowptr[base + i] = excl + loc[i];
        g_cursor[base + i] = excl + loc[i];
        g_dinv[base + i] = rsqrtf((float)dv[i] + 1.0f);
    }
    if (t == 1023) g_rowptr[NN] = excl + s;
}
__global__ void k_scatter(const int* __restrict__ ei) {
    int e = blockIdx.x * blockDim.x + threadIdx.x;
    if (e >= EE) return;
    int s = ei[e], d = ei[EE + e];
    int p = atomicAdd(&g_cursor[d], 1);
    g_col[p] = s;
    g_val[p] = g_dinv[s] * g_dinv[d];
}

// ---------------- CSR gather aggregations (float2 lanes, simple loops) --------
// y1 aggregation + scalar c aggregation + FUSED h1/h1cf epilogue
__global__ void k_agg64c(const float* __restrict__ in, const float* __restrict__ W1,
                         const float* __restrict__ b1, float* __restrict__ h1,
                         float* __restrict__ h1cf) {
    int w = (blockIdx.x * 256 + threadIdx.x) >> 5;
    int lane = threadIdx.x & 31;
    if (w >= NN) return;
    int s0 = g_rowptr[w], s1 = g_rowptr[w + 1];
    float2 a = make_float2(0.f, 0.f);
    float cacc = 0.f;
    for (int j = s0; j < s1; j++) {
        int s = g_col[j];
        float wt = g_val[j];
        float2 v = reinterpret_cast<const float2*>(in + s * 64)[lane];
        a.x += wt * v.x;  a.y += wt * v.y;
        cacc += wt * g_c[s];
    }
    float ws = g_dinv[w] * g_dinv[w];
    float2 v = reinterpret_cast<const float2*>(in + w * 64)[lane];
    a.x += ws * v.x;  a.y += ws * v.y;
    float aggc = cacc + ws * g_c[w];
    float2 bb = reinterpret_cast<const float2*>(b1)[lane];
    float2 w0 = reinterpret_cast<const float2*>(W1)[lane];  // enc_W1 row 0
    float2 h, hcf;
    h.x   = fmaxf(a.x + bb.x, 0.f);
    h.y   = fmaxf(a.y + bb.y, 0.f);
    hcf.x = fmaxf(a.x + aggc * w0.x + bb.x, 0.f);
    hcf.y = fmaxf(a.y + aggc * w0.y + bb.y, 0.f);
    reinterpret_cast<float2*>(h1 + w * 64)[lane] = h;
    reinterpret_cast<float2*>(h1cf + w * 64)[lane] = hcf;
}
__global__ void k_agg64x2(const float* __restrict__ in1, const float* __restrict__ in2,
                          float* __restrict__ out1, float* __restrict__ out2) {
    int w = (blockIdx.x * 256 + threadIdx.x) >> 5;
    int lane = threadIdx.x & 31;
    if (w >= NN) return;
    int s0 = g_rowptr[w], s1 = g_rowptr[w + 1];
    float2 a = make_float2(0.f, 0.f), b = make_float2(0.f, 0.f);
    for (int j = s0; j < s1; j++) {
        int s = g_col[j];
        float wt = g_val[j];
        float2 v1 = reinterpret_cast<const float2*>(in1 + s * 64)[lane];
        float2 v2 = reinterpret_cast<const float2*>(in2 + s * 64)[lane];
        a.x += wt * v1.x;  a.y += wt * v1.y;
        b.x += wt * v2.x;  b.y += wt * v2.y;
    }
    float ws = g_dinv[w] * g_dinv[w];
    float2 v1 = reinterpret_cast<const float2*>(in1 + w * 64)[lane];
    float2 v2 = reinterpret_cast<const float2*>(in2 + w * 64)[lane];
    a.x += ws * v1.x;  a.y += ws * v1.y;
    b.x += ws * v2.x;  b.y += ws * v2.y;
    reinterpret_cast<float2*>(out1 + w * 64)[lane] = a;
    reinterpret_cast<float2*>(out2 + w * 64)[lane] = b;
}
// decoder triple aggregation, SPLIT over gridDim.y (one input per y-slice)
__global__ void k_agg64x3() {
    int v = blockIdx.y;
    const float* tin = (v == 0) ? g_t1 : (v == 1) ? g_t2 : g_t3;
    float* tout      = (v == 0) ? g_at1 : (v == 1) ? g_at2 : g_at3;
    int w = (blockIdx.x * 256 + threadIdx.x) >> 5;
    int lane = threadIdx.x & 31;
    if (w >= NN) return;
    int s0 = g_rowptr[w], s1 = g_rowptr[w + 1];
    float2 a = make_float2(0.f, 0.f);
    for (int j = s0; j < s1; j++) {
        int s = g_col[j];
        float wt = g_val[j];
        float2 vv = reinterpret_cast<const float2*>(tin + s * 64)[lane];
        a.x += wt * vv.x;  a.y += wt * vv.y;
    }
    float ws = g_dinv[w] * g_dinv[w];
    float2 vv = reinterpret_cast<const float2*>(tin + w * 64)[lane];
    a.x += ws * vv.x;  a.y += ws * vv.y;
    reinterpret_cast<float2*>(tout + w * 64)[lane] = a;
}
__global__ void k_agg96(const float* __restrict__ z, const float* __restrict__ zcf) {
    int w = (blockIdx.x * 256 + threadIdx.x) >> 5;
    int lane = threadIdx.x & 31;
    if (w >= NN) return;
    int s0 = g_rowptr[w], s1 = g_rowptr[w + 1];
    float2 a = make_float2(0.f, 0.f);
    float c0 = 0.f;
    for (int j = s0; j < s1; j++) {
        int s = g_col[j];
        float wt = g_val[j];
        float2 v = reinterpret_cast<const float2*>(z + s * 64)[lane];
        a.x += wt * v.x;  a.y += wt * v.y;
        c0 += wt * zcf[s * 64 + lane];
    }
    float ws = g_dinv[w] * g_dinv[w];
    float2 v = reinterpret_cast<const float2*>(z + w * 64)[lane];
    a.x += ws * v.x;  a.y += ws * v.y;
    c0 += ws * zcf[w * 64 + lane];
    if (lane < 16) reinterpret_cast<float2*>(g_az + w * 32)[lane] = a;
    else           reinterpret_cast<float2*>(g_az2 + w * 32)[lane - 16] = a;
    g_azcf[w * 32 + lane] = c0;
}

// ---------------- GEMM bodies -------------------------------------------------
template <int KIN, int KOUT>
__device__ __forceinline__ float4 gemm4_compute(const float* __restrict__ A,
                                                const float* __restrict__ W,
                                                const float* __restrict__ b,
                                                int row, int c4) {
    float4 acc;
    if (b) { acc.x = b[c4]; acc.y = b[c4 + 1]; acc.z = b[c4 + 2]; acc.w = b[c4 + 3]; }
    else   { acc.x = acc.y = acc.z = acc.w = 0.f; }
    const float4* a4 = reinterpret_cast<const float4*>(A + row * KIN);
#pragma unroll 4
    for (int k4 = 0; k4 < KIN / 4; k4++) {
        float4 av = a4[k4];
        float4 w0 = *reinterpret_cast<const float4*>(&W[(k4 * 4 + 0) * KOUT + c4]);
        float4 w1 = *reinterpret_cast<const float4*>(&W[(k4 * 4 + 1) * KOUT + c4]);
        float4 w2 = *reinterpret_cast<const float4*>(&W[(k4 * 4 + 2) * KOUT + c4]);
        float4 w3 = *reinterpret_cast<const float4*>(&W[(k4 * 4 + 3) * KOUT + c4]);
        acc.x += av.x * w0.x + av.y * w1.x + av.z * w2.x + av.w * w3.x;
        acc.y += av.x * w0.y + av.y * w1.y + av.z * w2.y + av.w * w3.y;
        acc.z += av.x * w0.z + av.y * w1.z + av.z * w2.z + av.w * w3.z;
        acc.w += av.x * w0.w + av.y * w1.w + av.z * w2.w + av.w * w3.w;
    }
    return acc;
}
template <int KIN, int KOUT, bool RELU>
__global__ void k_gemm4(const float* __restrict__ A, const float* __restrict__ W,
                        const float* __restrict__ b, float* __restrict__ out) {
    constexpr int C4 = KOUT / 4;
    int idx = blockIdx.x * 256 + threadIdx.x;
    if (idx >= NN * C4) return;
    int row = idx / C4, c4 = (idx % C4) * 4;
    float4 acc = gemm4_compute<KIN, KOUT>(A, W, b, row, c4);
    if (RELU) {
        acc.x = fmaxf(acc.x, 0.f); acc.y = fmaxf(acc.y, 0.f);
        acc.z = fmaxf(acc.z, 0.f); acc.w = fmaxf(acc.w, 0.f);
    }
    *reinterpret_cast<float4*>(&out[row * KOUT + c4]) = acc;
}
// z GEMM with fused z_s / z_ns split outputs
__global__ void k_gemmz(const float* __restrict__ A, const float* __restrict__ W,
                        const float* __restrict__ b, float* __restrict__ z,
                        float* __restrict__ ozs, float* __restrict__ ozns) {
    int idx = blockIdx.x * 256 + threadIdx.x;
    if (idx >= NN * 16) return;
    int row = idx / 16, c4 = (idx % 16) * 4;
    float4 acc = gemm4_compute<64, 64>(A, W, b, row, c4);
    *reinterpret_cast<float4*>(&z[row * 64 + c4]) = acc;
    if (c4 < 32) *reinterpret_cast<float4*>(&ozs[row * 32 + c4]) = acc;
    else         *reinterpret_cast<float4*>(&ozns[row * 32 + c4 - 32]) = acc;
}
// four 32->64 GEMMs; v==3 (hs) emits bf16 hi/lo
__global__ void k_dec1(const float* __restrict__ d1W1, const float* __restrict__ d1b1,
                       const float* __restrict__ d2W1, const float* __restrict__ d2b1,
                       const float* __restrict__ sW, const float* __restrict__ sb) {
    int v = blockIdx.y;
    int idx = blockIdx.x * 256 + threadIdx.x;
    if (idx >= NN * 16) return;
    int row = idx / 16, c4 = (idx % 16) * 4;
    const float* A = (v == 0) ? g_az : (v == 2) ? g_azcf : g_az2;
    const float* W = (v == 1) ? d2W1 : (v == 3) ? sW : d1W1;
    const float* b = (v == 1) ? d2b1 : (v == 3) ? sb : d1b1;
    float4 acc = gemm4_compute<32, 64>(A, W, b, row, c4);
    if (v == 3) {
        float vals[4] = {acc.x, acc.y, acc.z, acc.w};
#pragma unroll
        for (int q = 0; q < 4; q++) {
            __nv_bfloat16 hi = __float2bfloat16(vals[q]);
            g_hshi[row * 64 + c4 + q] = hi;
            g_hslo[row * 64 + c4 + q] = __float2bfloat16(vals[q] - __bfloat162float(hi));
        }
    } else {
        acc.x = fmaxf(acc.x, 0.f); acc.y = fmaxf(acc.y, 0.f);
        acc.z = fmaxf(acc.z, 0.f); acc.w = fmaxf(acc.w, 0.f);
        float* out = (v == 0) ? g_t1 : (v == 1) ? g_t2 : g_t3;
        *reinterpret_cast<float4*>(&out[row * 64 + c4]) = acc;
    }
}
// three 64->256 GEMMs in one launch
__global__ void k_decout(const float* __restrict__ W1, const float* __restrict__ W2,
                         const float* __restrict__ b1, const float* __restrict__ b2,
                         float* __restrict__ o1, float* __restrict__ o2,
                         float* __restrict__ o3) {
    int v = blockIdx.y;
    int idx = blockIdx.x * 256 + threadIdx.x;
    if (idx >= NN * 64) return;
    int row = idx / 64, c4 = (idx % 64) * 4;
    const float* A = (v == 0) ? g_at1 : (v == 1) ? g_at2 : g_at3;
    const float* W = (v == 1) ? W2 : W1;
    const float* b = (v == 1) ? b2 : b1;
    float* out = (v == 0) ? o1 : (v == 1) ? o2 : o3;
    float4 acc = gemm4_compute<64, 256>(A, W, b, row, c4);
    *reinterpret_cast<float4*>(&out[row * 256 + c4]) = acc;
}

// ---------------- SYRK via mma.sync bf16 (hi/lo 3-product compensation) -------
#define SPITCH 72
#define TBYTES (128 * SPITCH * 2)   // 18432
#define OPITCH 133

static __device__ __forceinline__ void mma_bf16(float* d, const uint32_t* a,
                                                uint32_t b0, uint32_t b1) {
    asm volatile(
        "mma.sync.aligned.m16n8k16.row.col.f32.bf16.bf16.f32 "
        "{%0,%1,%2,%3}, {%4,%5,%6,%7}, {%8,%9}, {%0,%1,%2,%3};"
        : "+f"(d[0]), "+f"(d[1]), "+f"(d[2]), "+f"(d[3])
        : "r"(a[0]), "r"(a[1]), "r"(a[2]), "r"(a[3]), "r"(b0), "r"(b1));
}

__global__ void __launch_bounds__(256) k_syrk_mma(float* __restrict__ C) {
    int bi = blockIdx.y, bj = blockIdx.x;
    if (bj < bi) return;
    extern __shared__ char smem[];
    __nv_bfloat16* sAhi = reinterpret_cast<__nv_bfloat16*>(smem);
    __nv_bfloat16* sAlo = reinterpret_cast<__nv_bfloat16*>(smem + TBYTES);
    __nv_bfloat16* sBhi = reinterpret_cast<__nv_bfloat16*>(smem + 2 * TBYTES);
    __nv_bfloat16* sBlo = reinterpret_cast<__nv_bfloat16*>(smem + 3 * TBYTES);
    int tid = threadIdx.x;

    {
        const uint4* ga_hi = reinterpret_cast<const uint4*>(g_hshi + (size_t)bi * 128 * 64);
        const uint4* ga_lo = reinterpret_cast<const uint4*>(g_hslo + (size_t)bi * 128 * 64);
        const uint4* gb_hi = reinterpret_cast<const uint4*>(g_hshi + (size_t)bj * 128 * 64);
        const uint4* gb_lo = reinterpret_cast<const uint4*>(g_hslo + (size_t)bj * 128 * 64);
        for (int idx = tid; idx < 1024; idx += 256) {
            int row = idx >> 3, ch = idx & 7;
            int so = row * SPITCH + ch * 8;
            *reinterpret_cast<uint4*>(sAhi + so) = ga_hi[idx];
            *reinterpret_cast<uint4*>(sAlo + so) = ga_lo[idx];
            *reinterpret_cast<uint4*>(sBhi + so) = gb_hi[idx];
            *reinterpret_cast<uint4*>(sBlo + so) = gb_lo[idx];
        }
    }
    __syncthreads();

    int wid = tid >> 5, lane = tid & 31;
    int wr = wid >> 1, wc = wid & 1;
    int g = lane >> 2, tg = lane & 3;

    float acc[2][8][4];
#pragma unroll
    for (int mt = 0; mt < 2; mt++)
#pragma unroll
        for (int nt = 0; nt < 8; nt++)
#pragma unroll
            for (int q = 0; q < 4; q++) acc[mt][nt][q] = 0.f;

#pragma unroll
    for (int ks = 0; ks < 4; ks++) {
        int k0 = ks * 16;
        uint32_t aHi[2][4], aLo[2][4];
#pragma unroll
        for (int mt = 0; mt < 2; mt++) {
            int r = wr * 32 + mt * 16;
            aHi[mt][0] = *reinterpret_cast<const uint32_t*>(&sAhi[(r + g) * SPITCH + k0 + tg * 2]);
            aHi[mt][1] = *reinterpret_cast<const uint32_t*>(&sAhi[(r + g + 8) * SPITCH + k0 + tg * 2]);
            aHi[mt][2] = *reinterpret_cast<const uint32_t*>(&sAhi[(r + g) * SPITCH + k0 + tg * 2 + 8]);
            aHi[mt][3] = *reinterpret_cast<const uint32_t*>(&sAhi[(r + g + 8) * SPITCH + k0 + tg * 2 + 8]);
            aLo[mt][0] = *reinterpret_cast<const uint32_t*>(&sAlo[(r + g) * SPITCH + k0 + tg * 2]);
            aLo[mt][1] = *reinterpret_cast<const uint32_t*>(&sAlo[(r + g + 8) * SPITCH + k0 + tg * 2]);
            aLo[mt][2] = *reinterpret_cast<const uint32_t*>(&sAlo[(r + g) * SPITCH + k0 + tg * 2 + 8]);
            aLo[mt][3] = *reinterpret_cast<const uint32_t*>(&sAlo[(r + g + 8) * SPITCH + k0 + tg * 2 + 8]);
        }
#pragma unroll
        for (int nt = 0; nt < 8; nt++) {
            int n = wc * 64 + nt * 8 + g;
            uint32_t bh0 = *reinterpret_cast<const uint32_t*>(&sBhi[n * SPITCH + k0 + tg * 2]);
            uint32_t bh1 = *reinterpret_cast<const uint32_t*>(&sBhi[n * SPITCH + k0 + tg * 2 + 8]);
            uint32_t bl0 = *reinterpret_cast<const uint32_t*>(&sBlo[n * SPITCH + k0 + tg * 2]);
            uint32_t bl1 = *reinterpret_cast<const uint32_t*>(&sBlo[n * SPITCH + k0 + tg * 2 + 8]);
#pragma unroll
            for (int mt = 0; mt < 2; mt++) {
                mma_bf16(acc[mt][nt], aHi[mt], bh0, bh1);
                mma_bf16(acc[mt][nt], aHi[mt], bl0, bl1);
                mma_bf16(acc[mt][nt], aLo[mt], bh0, bh1);
            }
        }
    }
    __syncthreads();

    float* stage = reinterpret_cast<float*>(smem);   // [128][OPITCH]
#pragma unroll
    for (int mt = 0; mt < 2; mt++) {
        int r = wr * 32 + mt * 16 + g;
#pragma unroll
        for (int nt = 0; nt < 8; nt++) {
            int cc = wc * 64 + nt * 8 + tg * 2;
            stage[r * OPITCH + cc]           = acc[mt][nt][0];
            stage[r * OPITCH + cc + 1]       = acc[mt][nt][1];
            stage[(r + 8) * OPITCH + cc]     = acc[mt][nt][2];
            stage[(r + 8) * OPITCH + cc + 1] = acc[mt][nt][3];
        }
    }
    __syncthreads();

    for (int idx = tid; idx < 128 * 128; idx += 256) {
        int r2 = idx >> 7, c2 = idx & 127;
        C[(size_t)(bi * 128 + r2) * NN + bj * 128 + c2] = stage[r2 * OPITCH + c2];
    }
    if (bi != bj) {
        for (int idx = tid; idx < 128 * 128; idx += 256) {
            int r2 = idx >> 7, c2 = idx & 127;
            C[(size_t)(bj * 128 + r2) * NN + bi * 128 + c2] = stage[c2 * OPITCH + r2];
        }
    }
}

// ---------------- input-order hypotheses (round-3 validated) ------------------
static const int SIGS[6][16] = {
  {3145728,786432,16384,64,4096,64,2048,64,16384,256,2048,64,16384,256,2048,64},
  {2048,16384,64,256,2048,16384,64,256,786432,16384,4096,64,64,2048,64,3145728},
  {64,256,2048,16384,64,256,2048,16384,786432,64,64,16384,4096,64,2048,3145728},
  {64,2048,256,16384,64,2048,256,16384,64,2048,64,4096,64,16384,786432,3145728},
  {3145728,786432,16384,16384,16384,4096,2048,2048,2048,256,256,64,64,64,64,64},
  {64,64,64,64,64,256,256,2048,2048,2048,4096,16384,16384,16384,786432,3145728},
};
static const int MAPS[6][16] = {
  {0,1,2,3,4,5,6,7,8,9,10,11,12,13,14,15},
  {15,8,9,11,10,12,0,2,1,3,4,6,5,7,13,14},
  {15,8,11,9,12,10,2,0,3,1,6,4,7,5,14,13},
  {15,14,13,12,11,10,9,8,7,6,5,4,3,2,1,0},
  {0,1,2,11,5,12,6,13,3,9,7,14,4,10,8,15},
  {15,14,11,0,10,1,7,2,12,5,8,3,13,6,9,4},
};

// ---------------- launch ------------------------------------------------------
extern "C" void kernel_launch(void* const* d_in, const int* in_sizes, int n_in,
                              void* d_out, int out_size) {
    static bool init_done = false;
    if (!init_done) {
        cudaFuncSetAttribute(k_syrk_mma, cudaFuncAttributeMaxDynamicSharedMemorySize,
                             4 * TBYTES);
        init_done = true;
    }

    const int* map = MAPS[0];
    for (int h = 0; h < 6; h++) {
        bool ok = (n_in >= 16);
        for (int i = 0; ok && i < 16; i++) ok = (in_sizes[i] == SIGS[h][i]);
        if (ok) { map = MAPS[h]; break; }
    }
    const float* x      = (const float*)d_in[map[0]];
    const int*   ei     = (const int*)  d_in[map[1]];
    const float* enc_W1 = (const float*)d_in[map[2]];
    const float* enc_b1 = (const float*)d_in[map[3]];
    const float* enc_W2 = (const float*)d_in[map[4]];
    const float* enc_b2 = (const float*)d_in[map[5]];
    const float* d1_W1  = (const float*)d_in[map[6]];
    const float* d1_b1  = (const float*)d_in[map[7]];
    const float* d1_W2  = (const float*)d_in[map[8]];
    const float* d1_b2  = (const float*)d_in[map[9]];
    const float* d2_W1  = (const float*)d_in[map[10]];
    const float* d2_b1  = (const float*)d_in[map[11]];
    const float* d2_W2  = (const float*)d_in[map[12]];
    const float* d2_b2  = (const float*)d_in[map[13]];
    const float* s_W    = (const float*)d_in[map[14]];
    const float* s_b    = (const float*)d_in[map[15]];
    float* out = (float*)d_out;

    float* o_zs   = out;
    float* o_zns  = out + (size_t)NN * 32;
    float* o_xs   = out + (size_t)NN * 64;
    float* o_xns  = o_xs + (size_t)NN * 256;
    float* o_xscf = o_xns + (size_t)NN * 256;
    float* o_s    = o_xscf + (size_t)NN * 256;   // [N,N] written LAST

    // encoder scratch in o_s (all consumed before SYRK)
    const size_t CH = (size_t)NN * 64;
    float* sc_y1   = o_s + 0 * CH;
    float* sc_h1   = o_s + 1 * CH;
    float* sc_h1cf = o_s + 2 * CH;
    float* sc_B    = o_s + 3 * CH;
    float* sc_Bcf  = o_s + 4 * CH;
    float* sc_z    = o_s + 5 * CH;
    float* sc_zcf  = o_s + 6 * CH;

    const int TB = 256;
    const int gN   = (NN + TB - 1) / TB;
    const int gE   = (EE + TB - 1) / TB;
    const int gN32 = (NN * 32 + TB - 1) / TB;
    const int gN64 = (NN * 64 + TB - 1) / TB;
    const int gN16 = (NN * 16 + TB - 1) / TB;

    // CSR build (+ fused cvec)
    k_init0<<<gN, TB>>>(x);
    k_count<<<gE, TB>>>(ei);
    k_scan<<<1, 1024>>>();
    k_scatter<<<gE, TB>>>(ei);

    // encoder conv1 (GEMM + fused agg/h1)
    k_gemm4<INDIM, 64, false><<<gN16, TB>>>(x, enc_W1, nullptr, sc_y1);
    k_agg64c<<<gN32, TB>>>(sc_y1, enc_W1, enc_b1, sc_h1, sc_h1cf);

    // encoder conv2 (fused split in gemmz)
    k_agg64x2<<<gN32, TB>>>(sc_h1, sc_h1cf, sc_B, sc_Bcf);
    k_gemmz<<<gN16, TB>>>(sc_B, enc_W2, enc_b2, sc_z, o_zs, o_zns);
    k_gemm4<64, 64, false><<<gN16, TB>>>(sc_Bcf, enc_W2, enc_b2, sc_zcf);

    // fused aggregation of z_s / z_ns / z_s_cf
    k_agg96<<<gN32, TB>>>(sc_z, sc_zcf);

    // decoder first layers + hs (v==3 writes bf16 hi/lo)
    dim3 dg1(gN16, 4);
    k_dec1<<<dg1, TB>>>(d1_W1, d1_b1, d2_W1, d2_b1, s_W, s_b);

    // decoder tail (triple aggregation split over y; then output GEMMs)
    dim3 dga(gN32, 3);
    k_agg64x3<<<dga, TB>>>();
    dim3 dog(gN64, 3);
    k_decout<<<dog, TB>>>(d1_W2, d2_W2, d1_b2, d2_b2, o_xs, o_xns, o_xscf);

    // tensor-core SYRK last
    dim3 syrk_grid(NN / 128, NN / 128);
    k_syrk_mma<<<syrk_grid, 256, 4 * TBYTES>>>(o_s);
}

// round 16
// speedup vs baseline: 1.1203x; 1.0242x over previous
#include <cuda_runtime.h>
#include <cuda_bf16.h>
#include <cstdint>

#define NN 12288
#define EE 393216
#define INDIM 256
#define HID 64
#define ELLW 96
#define NT 96
#define NTRI (NT * (NT + 1) / 2)   // 4656

// ---------------- static device scratch (device-code references ONLY) ---------
__device__ int   g_deg[NN];
__device__ float g_dinv[NN];
__device__ int   g_colell[NN * ELLW];
__device__ int2  g_tilemap[NTRI];
__device__ float g_c[NN];
__device__ __nv_bfloat16 g_hshi[NN * HID];
__device__ __nv_bfloat16 g_hslo[NN * HID];
__device__ float g_az[NN * 32];
__device__ float g_az2[NN * 32];
__device__ float g_azcf[NN * 32];
__device__ float g_t1[NN * 64];
__device__ float g_t2[NN * 64];
__device__ float g_t3[NN * 64];
__device__ float g_at1[NN * 64];
__device__ float g_at2[NN * 64];
__device__ float g_at3[NN * 64];

// ---------------- init: zero degrees + cvec + SYRK tile map -------------------
__global__ void k_init0(const float* __restrict__ x) {
    int i = blockIdx.x * blockDim.x + threadIdx.x;
    if (i < NN) {
        g_deg[i] = 0;
        g_c[i] = 1.0f - 2.0f * x[i * INDIM];
    }
    if (i < NTRI) {
        double tt = (double)i;
        int bi = (int)((2.0 * NT + 1.0 -
                        sqrt((2.0 * NT + 1.0) * (2.0 * NT + 1.0) - 8.0 * tt)) * 0.5);
        if (bi < 0) bi = 0;
        if (bi > NT - 1) bi = NT - 1;
        while (bi > 0 && bi * NT - bi * (bi - 1) / 2 > i) bi--;
        while ((bi + 1) * NT - (bi + 1) * bi / 2 <= i) bi++;
        int bj = bi + (i - (bi * NT - bi * (bi - 1) / 2));
        g_tilemap[i] = make_int2(bi, bj);
    }
}
// ELL scatter: no count pass, no scan
__global__ void k_scatter(const int* __restrict__ ei) {
    int e = blockIdx.x * blockDim.x + threadIdx.x;
    if (e >= EE) return;
    int s = ei[e], d = ei[EE + e];
    int pos = atomicAdd(&g_deg[d], 1);
    g_colell[d * ELLW + pos] = s;
}
__global__ void k_dinv() {
    int i = blockIdx.x * blockDim.x + threadIdx.x;
    if (i < NN) g_dinv[i] = rsqrtf((float)g_deg[i] + 1.0f);
}

// ---------------- ELL gather aggregations (float2 lanes) ----------------------
// y1 aggregation + scalar c aggregation + FUSED h1/h1cf epilogue
__global__ void k_agg64c(const float* __restrict__ in, const float* __restrict__ W1,
                         const float* __restrict__ b1, float* __restrict__ h1,
                         float* __restrict__ h1cf) {
    int w = (blockIdx.x * 256 + threadIdx.x) >> 5;
    int lane = threadIdx.x & 31;
    if (w >= NN) return;
    int dg = g_deg[w];
    const int* cptr = g_colell + w * ELLW;
    float dw = g_dinv[w];
    float2 a = make_float2(0.f, 0.f);
    float cacc = 0.f;
    for (int j = 0; j < dg; j++) {
        int s = cptr[j];
        float wt = g_dinv[s] * dw;
        float2 v = reinterpret_cast<const float2*>(in + s * 64)[lane];
        a.x += wt * v.x;  a.y += wt * v.y;
        cacc += wt * g_c[s];
    }
    float ws = dw * dw;
    float2 v = reinterpret_cast<const float2*>(in + w * 64)[lane];
    a.x += ws * v.x;  a.y += ws * v.y;
    float aggc = cacc + ws * g_c[w];
    float2 bb = reinterpret_cast<const float2*>(b1)[lane];
    float2 w0 = reinterpret_cast<const float2*>(W1)[lane];  // enc_W1 row 0
    float2 h, hcf;
    h.x   = fmaxf(a.x + bb.x, 0.f);
    h.y   = fmaxf(a.y + bb.y, 0.f);
    hcf.x = fmaxf(a.x + aggc * w0.x + bb.x, 0.f);
    hcf.y = fmaxf(a.y + aggc * w0.y + bb.y, 0.f);
    reinterpret_cast<float2*>(h1 + w * 64)[lane] = h;
    reinterpret_cast<float2*>(h1cf + w * 64)[lane] = hcf;
}
__global__ void k_agg64x2(const float* __restrict__ in1, const float* __restrict__ in2,
                          float* __restrict__ out1, float* __restrict__ out2) {
    int w = (blockIdx.x * 256 + threadIdx.x) >> 5;
    int lane = threadIdx.x & 31;
    if (w >= NN) return;
    int dg = g_deg[w];
    const int* cptr = g_colell + w * ELLW;
    float dw = g_dinv[w];
    float2 a = make_float2(0.f, 0.f), b = make_float2(0.f, 0.f);
    for (int j = 0; j < dg; j++) {
        int s = cptr[j];
        float wt = g_dinv[s] * dw;
        float2 v1 = reinterpret_cast<const float2*>(in1 + s * 64)[lane];
        float2 v2 = reinterpret_cast<const float2*>(in2 + s * 64)[lane];
        a.x += wt * v1.x;  a.y += wt * v1.y;
        b.x += wt * v2.x;  b.y += wt * v2.y;
    }
    float ws = dw * dw;
    float2 v1 = reinterpret_cast<const float2*>(in1 + w * 64)[lane];
    float2 v2 = reinterpret_cast<const float2*>(in2 + w * 64)[lane];
    a.x += ws * v1.x;  a.y += ws * v1.y;
    b.x += ws * v2.x;  b.y += ws * v2.y;
    reinterpret_cast<float2*>(out1 + w * 64)[lane] = a;
    reinterpret_cast<float2*>(out2 + w * 64)[lane] = b;
}
// decoder triple aggregation, split over gridDim.y
__global__ void k_agg64x3() {
    int v = blockIdx.y;
    const float* tin = (v == 0) ? g_t1 : (v == 1) ? g_t2 : g_t3;
    float* tout      = (v == 0) ? g_at1 : (v == 1) ? g_at2 : g_at3;
    int w = (blockIdx.x * 256 + threadIdx.x) >> 5;
    int lane = threadIdx.x & 31;
    if (w >= NN) return;
    int dg = g_deg[w];
    const int* cptr = g_colell + w * ELLW;
    float dw = g_dinv[w];
    float2 a = make_float2(0.f, 0.f);
    for (int j = 0; j < dg; j++) {
        int s = cptr[j];
        float wt = g_dinv[s] * dw;
        float2 vv = reinterpret_cast<const float2*>(tin + s * 64)[lane];
        a.x += wt * vv.x;  a.y += wt * vv.y;
    }
    float ws = dw * dw;
    float2 vv = reinterpret_cast<const float2*>(tin + w * 64)[lane];
    a.x += ws * vv.x;  a.y += ws * vv.y;
    reinterpret_cast<float2*>(tout + w * 64)[lane] = a;
}
__global__ void k_agg96(const float* __restrict__ z, const float* __restrict__ zcf) {
    int w = (blockIdx.x * 256 + threadIdx.x) >> 5;
    int lane = threadIdx.x & 31;
    if (w >= NN) return;
    int dg = g_deg[w];
    const int* cptr = g_colell + w * ELLW;
    float dw = g_dinv[w];
    float2 a = make_float2(0.f, 0.f);
    float c0 = 0.f;
    for (int j = 0; j < dg; j++) {
        int s = cptr[j];
        float wt = g_dinv[s] * dw;
        float2 v = reinterpret_cast<const float2*>(z + s * 64)[lane];
        a.x += wt * v.x;  a.y += wt * v.y;
        c0 += wt * zcf[s * 64 + lane];
    }
    float ws = dw * dw;
    float2 v = reinterpret_cast<const float2*>(z + w * 64)[lane];
    a.x += ws * v.x;  a.y += ws * v.y;
    c0 += ws * zcf[w * 64 + lane];
    if (lane < 16) reinterpret_cast<float2*>(g_az + w * 32)[lane] = a;
    else           reinterpret_cast<float2*>(g_az2 + w * 32)[lane - 16] = a;
    g_azcf[w * 32 + lane] = c0;
}

// ---------------- GEMM bodies -------------------------------------------------
template <int KIN, int KOUT>
__device__ __forceinline__ float4 gemm4_compute(const float* __restrict__ A,
                                                const float* __restrict__ W,
                                                const float* __restrict__ b,
                                                int row, int c4) {
    float4 acc;
    if (b) { acc.x = b[c4]; acc.y = b[c4 + 1]; acc.z = b[c4 + 2]; acc.w = b[c4 + 3]; }
    else   { acc.x = acc.y = acc.z = acc.w = 0.f; }
    const float4* a4 = reinterpret_cast<const float4*>(A + row * KIN);
#pragma unroll 4
    for (int k4 = 0; k4 < KIN / 4; k4++) {
        float4 av = a4[k4];
        float4 w0 = *reinterpret_cast<const float4*>(&W[(k4 * 4 + 0) * KOUT + c4]);
        float4 w1 = *reinterpret_cast<const float4*>(&W[(k4 * 4 + 1) * KOUT + c4]);
        float4 w2 = *reinterpret_cast<const float4*>(&W[(k4 * 4 + 2) * KOUT + c4]);
        float4 w3 = *reinterpret_cast<const float4*>(&W[(k4 * 4 + 3) * KOUT + c4]);
        acc.x += av.x * w0.x + av.y * w1.x + av.z * w2.x + av.w * w3.x;
        acc.y += av.x * w0.y + av.y * w1.y + av.z * w2.y + av.w * w3.y;
        acc.z += av.x * w0.z + av.y * w1.z + av.z * w2.z + av.w * w3.z;
        acc.w += av.x * w0.w + av.y * w1.w + av.z * w2.w + av.w * w3.w;
    }
    return acc;
}
template <int KIN, int KOUT, bool RELU>
__global__ void k_gemm4(const float* __restrict__ A, const float* __restrict__ W,
                        const float* __restrict__ b, float* __restrict__ out) {
    constexpr int C4 = KOUT / 4;
    int idx = blockIdx.x * 256 + threadIdx.x;
    if (idx >= NN * C4) return;
    int row = idx / C4, c4 = (idx % C4) * 4;
    float4 acc = gemm4_compute<KIN, KOUT>(A, W, b, row, c4);
    if (RELU) {
        acc.x = fmaxf(acc.x, 0.f); acc.y = fmaxf(acc.y, 0.f);
        acc.z = fmaxf(acc.z, 0.f); acc.w = fmaxf(acc.w, 0.f);
    }
    *reinterpret_cast<float4*>(&out[row * KOUT + c4]) = acc;
}
// both z GEMMs in one launch; v==0 also writes split z_s/z_ns outputs
__global__ void k_gemmz(const float* __restrict__ B, const float* __restrict__ Bcf,
                        const float* __restrict__ W, const float* __restrict__ b,
                        float* __restrict__ z, float* __restrict__ zcf,
                        float* __restrict__ ozs, float* __restrict__ ozns) {
    int v = blockIdx.y;
    int idx = blockIdx.x * 256 + threadIdx.x;
    if (idx >= NN * 16) return;
    int row = idx / 16, c4 = (idx % 16) * 4;
    const float* A = (v == 0) ? B : Bcf;
    float4 acc = gemm4_compute<64, 64>(A, W, b, row, c4);
    if (v == 0) {
        *reinterpret_cast<float4*>(&z[row * 64 + c4]) = acc;
        if (c4 < 32) *reinterpret_cast<float4*>(&ozs[row * 32 + c4]) = acc;
        else         *reinterpret_cast<float4*>(&ozns[row * 32 + c4 - 32]) = acc;
    } else {
        *reinterpret_cast<float4*>(&zcf[row * 64 + c4]) = acc;
    }
}
// four 32->64 GEMMs; v==3 (hs) emits bf16 hi/lo
__global__ void k_dec1(const float* __restrict__ d1W1, const float* __restrict__ d1b1,
                       const float* __restrict__ d2W1, const float* __restrict__ d2b1,
                       const float* __restrict__ sW, const float* __restrict__ sb) {
    int v = blockIdx.y;
    int idx = blockIdx.x * 256 + threadIdx.x;
    if (idx >= NN * 16) return;
    int row = idx / 16, c4 = (idx % 16) * 4;
    const float* A = (v == 0) ? g_az : (v == 2) ? g_azcf : g_az2;
    const float* W = (v == 1) ? d2W1 : (v == 3) ? sW : d1W1;
    const float* b = (v == 1) ? d2b1 : (v == 3) ? sb : d1b1;
    float4 acc = gemm4_compute<32, 64>(A, W, b, row, c4);
    if (v == 3) {
        float vals[4] = {acc.x, acc.y, acc.z, acc.w};
#pragma unroll
        for (int q = 0; q < 4; q++) {
            __nv_bfloat16 hi = __float2bfloat16(vals[q]);
            g_hshi[row * 64 + c4 + q] = hi;
            g_hslo[row * 64 + c4 + q] = __float2bfloat16(vals[q] - __bfloat162float(hi));
        }
    } else {
        acc.x = fmaxf(acc.x, 0.f); acc.y = fmaxf(acc.y, 0.f);
        acc.z = fmaxf(acc.z, 0.f); acc.w = fmaxf(acc.w, 0.f);
        float* out = (v == 0) ? g_t1 : (v == 1) ? g_t2 : g_t3;
        *reinterpret_cast<float4*>(&out[row * 64 + c4]) = acc;
    }
}
// three 64->256 GEMMs in one launch
__global__ void k_decout(const float* __restrict__ W1, const float* __restrict__ W2,
                         const float* __restrict__ b1, const float* __restrict__ b2,
                         float* __restrict__ o1, float* __restrict__ o2,
                         float* __restrict__ o3) {
    int v = blockIdx.y;
    int idx = blockIdx.x * 256 + threadIdx.x;
    if (idx >= NN * 64) return;
    int row = idx / 64, c4 = (idx % 64) * 4;
    const float* A = (v == 0) ? g_at1 : (v == 1) ? g_at2 : g_at3;
    const float* W = (v == 1) ? W2 : W1;
    const float* b = (v == 1) ? b2 : b1;
    float* out = (v == 0) ? o1 : (v == 1) ? o2 : o3;
    float4 acc = gemm4_compute<64, 256>(A, W, b, row, c4);
    *reinterpret_cast<float4*>(&out[row * 256 + c4]) = acc;
}

// ---------------- SYRK via mma.sync bf16 (hi/lo 3-product compensation) -------
#define SPITCH 72
#define TBYTES (128 * SPITCH * 2)   // 18432
#define OPITCH 133

static __device__ __forceinline__ void mma_bf16(float* d, const uint32_t* a,
                                                uint32_t b0, uint32_t b1) {
    asm volatile(
        "mma.sync.aligned.m16n8k16.row.col.f32.bf16.bf16.f32 "
        "{%0,%1,%2,%3}, {%4,%5,%6,%7}, {%8,%9}, {%0,%1,%2,%3};"
        : "+f"(d[0]), "+f"(d[1]), "+f"(d[2]), "+f"(d[3])
        : "r"(a[0]), "r"(a[1]), "r"(a[2]), "r"(a[3]), "r"(b0), "r"(b1));
}

__global__ void __launch_bounds__(256) k_syrk_mma(float* __restrict__ C) {
    int2 tm = g_tilemap[blockIdx.x];
    int bi = tm.x, bj = tm.y;
    extern __shared__ char smem[];
    __nv_bfloat16* sAhi = reinterpret_cast<__nv_bfloat16*>(smem);
    __nv_bfloat16* sAlo = reinterpret_cast<__nv_bfloat16*>(smem + TBYTES);
    __nv_bfloat16* sBhi = reinterpret_cast<__nv_bfloat16*>(smem + 2 * TBYTES);
    __nv_bfloat16* sBlo = reinterpret_cast<__nv_bfloat16*>(smem + 3 * TBYTES);
    int tid = threadIdx.x;

    {
        const uint4* ga_hi = reinterpret_cast<const uint4*>(g_hshi + (size_t)bi * 128 * 64);
        const uint4* ga_lo = reinterpret_cast<const uint4*>(g_hslo + (size_t)bi * 128 * 64);
        const uint4* gb_hi = reinterpret_cast<const uint4*>(g_hshi + (size_t)bj * 128 * 64);
        const uint4* gb_lo = reinterpret_cast<const uint4*>(g_hslo + (size_t)bj * 128 * 64);
        for (int idx = tid; idx < 1024; idx += 256) {
            int row = idx >> 3, ch = idx & 7;
            int so = row * SPITCH + ch * 8;
            *reinterpret_cast<uint4*>(sAhi + so) = ga_hi[idx];
            *reinterpret_cast<uint4*>(sAlo + so) = ga_lo[idx];
            *reinterpret_cast<uint4*>(sBhi + so) = gb_hi[idx];
            *reinterpret_cast<uint4*>(sBlo + so) = gb_lo[idx];
        }
    }
    __syncthreads();

    int wid = tid >> 5, lane = tid & 31;
    int wr = wid >> 1, wc = wid & 1;
    int g = lane >> 2, tg = lane & 3;

    float acc[2][8][4];
#pragma unroll
    for (int mt = 0; mt < 2; mt++)
#pragma unroll
        for (int nt = 0; nt < 8; nt++)
#pragma unroll
            for (int q = 0; q < 4; q++) acc[mt][nt][q] = 0.f;

#pragma unroll
    for (int ks = 0; ks < 4; ks++) {
        int k0 = ks * 16;
        uint32_t aHi[2][4], aLo[2][4];
#pragma unroll
        for (int mt = 0; mt < 2; mt++) {
            int r = wr * 32 + mt * 16;
            aHi[mt][0] = *reinterpret_cast<const uint32_t*>(&sAhi[(r + g) * SPITCH + k0 + tg * 2]);
            aHi[mt][1] = *reinterpret_cast<const uint32_t*>(&sAhi[(r + g + 8) * SPITCH + k0 + tg * 2]);
            aHi[mt][2] = *reinterpret_cast<const uint32_t*>(&sAhi[(r + g) * SPITCH + k0 + tg * 2 + 8]);
            aHi[mt][3] = *reinterpret_cast<const uint32_t*>(&sAhi[(r + g + 8) * SPITCH + k0 + tg * 2 + 8]);
            aLo[mt][0] = *reinterpret_cast<const uint32_t*>(&sAlo[(r + g) * SPITCH + k0 + tg * 2]);
            aLo[mt][1] = *reinterpret_cast<const uint32_t*>(&sAlo[(r + g + 8) * SPITCH + k0 + tg * 2]);
            aLo[mt][2] = *reinterpret_cast<const uint32_t*>(&sAlo[(r + g) * SPITCH + k0 + tg * 2 + 8]);
            aLo[mt][3] = *reinterpret_cast<const uint32_t*>(&sAlo[(r + g + 8) * SPITCH + k0 + tg * 2 + 8]);
        }
#pragma unroll
        for (int nt = 0; nt < 8; nt++) {
            int n = wc * 64 + nt * 8 + g;
            uint32_t bh0 = *reinterpret_cast<const uint32_t*>(&sBhi[n * SPITCH + k0 + tg * 2]);
            uint32_t bh1 = *reinterpret_cast<const uint32_t*>(&sBhi[n * SPITCH + k0 + tg * 2 + 8]);
            uint32_t bl0 = *reinterpret_cast<const uint32_t*>(&sBlo[n * SPITCH + k0 + tg * 2]);
            uint32_t bl1 = *reinterpret_cast<const uint32_t*>(&sBlo[n * SPITCH + k0 + tg * 2 + 8]);
#pragma unroll
            for (int mt = 0; mt < 2; mt++) {
                mma_bf16(acc[mt][nt], aHi[mt], bh0, bh1);
                mma_bf16(acc[mt][nt], aHi[mt], bl0, bl1);
                mma_bf16(acc[mt][nt], aLo[mt], bh0, bh1);
            }
        }
    }
    __syncthreads();

    float* stage = reinterpret_cast<float*>(smem);   // [128][OPITCH]
#pragma unroll
    for (int mt = 0; mt < 2; mt++) {
        int r = wr * 32 + mt * 16 + g;
#pragma unroll
        for (int nt = 0; nt < 8; nt++) {
            int cc = wc * 64 + nt * 8 + tg * 2;
            stage[r * OPITCH + cc]           = acc[mt][nt][0];
            stage[r * OPITCH + cc + 1]       = acc[mt][nt][1];
            stage[(r + 8) * OPITCH + cc]     = acc[mt][nt][2];
            stage[(r + 8) * OPITCH + cc + 1] = acc[mt][nt][3];
        }
    }
    __syncthreads();

    for (int idx = tid; idx < 128 * 128; idx += 256) {
        int r2 = idx >> 7, c2 = idx & 127;
        C[(size_t)(bi * 128 + r2) * NN + bj * 128 + c2] = stage[r2 * OPITCH + c2];
    }
    if (bi != bj) {
        for (int idx = tid; idx < 128 * 128; idx += 256) {
            int r2 = idx >> 7, c2 = idx & 127;
            C[(size_t)(bj * 128 + r2) * NN + bi * 128 + c2] = stage[c2 * OPITCH + r2];
        }
    }
}

// ---------------- input-order hypotheses (round-3 validated) ------------------
static const int SIGS[6][16] = {
  {3145728,786432,16384,64,4096,64,2048,64,16384,256,2048,64,16384,256,2048,64},
  {2048,16384,64,256,2048,16384,64,256,786432,16384,4096,64,64,2048,64,3145728},
  {64,256,2048,16384,64,256,2048,16384,786432,64,64,16384,4096,64,2048,3145728},
  {64,2048,256,16384,64,2048,256,16384,64,2048,64,4096,64,16384,786432,3145728},
  {3145728,786432,16384,16384,16384,4096,2048,2048,2048,256,256,64,64,64,64,64},
  {64,64,64,64,64,256,256,2048,2048,2048,4096,16384,16384,16384,786432,3145728},
};
static const int MAPS[6][16] = {
  {0,1,2,3,4,5,6,7,8,9,10,11,12,13,14,15},
  {15,8,9,11,10,12,0,2,1,3,4,6,5,7,13,14},
  {15,8,11,9,12,10,2,0,3,1,6,4,7,5,14,13},
  {15,14,13,12,11,10,9,8,7,6,5,4,3,2,1,0},
  {0,1,2,11,5,12,6,13,3,9,7,14,4,10,8,15},
  {15,14,11,0,10,1,7,2,12,5,8,3,13,6,9,4},
};

// ---------------- launch ------------------------------------------------------
extern "C" void kernel_launch(void* const* d_in, const int* in_sizes, int n_in,
                              void* d_out, int out_size) {
    static bool init_done = false;
    if (!init_done) {
        cudaFuncSetAttribute(k_syrk_mma, cudaFuncAttributeMaxDynamicSharedMemorySize,
                             4 * TBYTES);
        init_done = true;
    }

    const int* map = MAPS[0];
    for (int h = 0; h < 6; h++) {
        bool ok = (n_in >= 16);
        for (int i = 0; ok && i < 16; i++) ok = (in_sizes[i] == SIGS[h][i]);
        if (ok) { map = MAPS[h]; break; }
    }
    const float* x      = (const float*)d_in[map[0]];
    const int*   ei     = (const int*)  d_in[map[1]];
    const float* enc_W1 = (const float*)d_in[map[2]];
    const float* enc_b1 = (const float*)d_in[map[3]];
    const float* enc_W2 = (const float*)d_in[map[4]];
    const float* enc_b2 = (const float*)d_in[map[5]];
    const float* d1_W1  = (const float*)d_in[map[6]];
    const float* d1_b1  = (const float*)d_in[map[7]];
    const float* d1_W2  = (const float*)d_in[map[8]];
    const float* d1_b2  = (const float*)d_in[map[9]];
    const float* d2_W1  = (const float*)d_in[map[10]];
    const float* d2_b1  = (const float*)d_in[map[11]];
    const float* d2_W2  = (const float*)d_in[map[12]];
    const float* d2_b2  = (const float*)d_in[map[13]];
    const float* s_W    = (const float*)d_in[map[14]];
    const float* s_b    = (const float*)d_in[map[15]];
    float* out = (float*)d_out;

    float* o_zs   = out;
    float* o_zns  = out + (size_t)NN * 32;
    float* o_xs   = out + (size_t)NN * 64;
    float* o_xns  = o_xs + (size_t)NN * 256;
    float* o_xscf = o_xns + (size_t)NN * 256;
    float* o_s    = o_xscf + (size_t)NN * 256;   // [N,N] written LAST

    // encoder scratch in o_s (all consumed before SYRK)
    const size_t CH = (size_t)NN * 64;
    float* sc_y1   = o_s + 0 * CH;
    float* sc_h1   = o_s + 1 * CH;
    float* sc_h1cf = o_s + 2 * CH;
    float* sc_B    = o_s + 3 * CH;
    float* sc_Bcf  = o_s + 4 * CH;
    float* sc_z    = o_s + 5 * CH;
    float* sc_zcf  = o_s + 6 * CH;

    const int TB = 256;
    const int gN   = (NN + TB - 1) / TB;
    const int gE   = (EE + TB - 1) / TB;
    const int gN32 = (NN * 32 + TB - 1) / TB;
    const int gN64 = (NN * 64 + TB - 1) / TB;
    const int gN16 = (NN * 16 + TB - 1) / TB;

    // graph build: ELL scatter (no count, no scan)
    k_init0<<<gN, TB>>>(x);
    k_scatter<<<gE, TB>>>(ei);
    k_dinv<<<gN, TB>>>();

    // encoder conv1 (GEMM + fused agg/h1)
    k_gemm4<INDIM, 64, false><<<gN16, TB>>>(x, enc_W1, nullptr, sc_y1);
    k_agg64c<<<gN32, TB>>>(sc_y1, enc_W1, enc_b1, sc_h1, sc_h1cf);

    // encoder conv2 (both z GEMMs in one launch; split fused)
    k_agg64x2<<<gN32, TB>>>(sc_h1, sc_h1cf, sc_B, sc_Bcf);
    dim3 zg(gN16, 2);
    k_gemmz<<<zg, TB>>>(sc_B, sc_Bcf, enc_W2, enc_b2, sc_z, sc_zcf, o_zs, o_zns);

    // fused aggregation of z_s / z_ns / z_s_cf
    k_agg96<<<gN32, TB>>>(sc_z, sc_zcf);

    // decoder first layers + hs (v==3 writes bf16 hi/lo)
    dim3 dg1(gN16, 4);
    k_dec1<<<dg1, TB>>>(d1_W1, d1_b1, d2_W1, d2_b1, s_W, s_b);

    // decoder tail
    dim3 dga(gN32, 3);
    k_agg64x3<<<dga, TB>>>();
    dim3 dog(gN64, 3);
    k_decout<<<dog, TB>>>(d1_W2, d2_W2, d1_b2, d2_b2, o_xs, o_xns, o_xscf);

    // tensor-core SYRK last (dense triangular grid via tile map)
    k_syrk_mma<<<NTRI, 256, 4 * TBYTES>>>(o_s);
}